// round 7
// baseline (speedup 1.0000x reference)
#include <cuda_runtime.h>

// Problem constants
#define B_  8
#define N_  1024
#define C_  64
#define O_  64
#define KM  4          // K+1
#define BN  (B_*N_)    // 8192

// -------- device scratch --------
__device__ float g_sRi[BN], g_sIi[BN], g_sRj[BN], g_sIj[BN];
__device__ float g_rsum[BN];   // 1 / sum_i exp(mag[b,i,j]) per (b,j)

// ============================================================
// Kernel 1: per-(b,n) attention projections. One warp per (b,n).
// ============================================================
__global__ void __launch_bounds__(256) k1_proj(
    const float* __restrict__ Xr, const float* __restrict__ Xi,
    const float* __restrict__ awr, const float* __restrict__ awi,
    const float* __restrict__ abr, const float* __restrict__ abi)
{
    int warp = (blockIdx.x * blockDim.x + threadIdx.x) >> 5;
    int lane = threadIdx.x & 31;
    if (warp >= BN) return;
    const float* xr = Xr + warp * C_;
    const float* xi = Xi + warp * C_;
    float sRi = 0.f, sIi = 0.f, sRj = 0.f, sIj = 0.f;
#pragma unroll
    for (int t = 0; t < 2; t++) {
        int c = lane + t * 32;
        float a = xr[c], b = xi[c];
        float wri = awr[c],      wii = awi[c];
        float wrj = awr[C_ + c], wij = awi[C_ + c];
        sRi += a * wri - b * wii;
        sIi += a * wii + b * wri;
        sRj += a * wrj - b * wij;
        sIj += a * wij + b * wrj;
    }
#pragma unroll
    for (int off = 16; off; off >>= 1) {
        sRi += __shfl_xor_sync(0xffffffffu, sRi, off);
        sIi += __shfl_xor_sync(0xffffffffu, sIi, off);
        sRj += __shfl_xor_sync(0xffffffffu, sRj, off);
        sIj += __shfl_xor_sync(0xffffffffu, sIj, off);
    }
    if (lane == 0) {
        g_sRi[warp] = sRi + abr[0];
        g_sIi[warp] = sIi + abi[0];
        g_sRj[warp] = sRj;
        g_sIj[warp] = sIj;
    }
}

// ============================================================
// Kernel 2: softmax denominator per (b,j): sum over i of exp(mag).
// ============================================================
__global__ void __launch_bounds__(128) k2_sumexp(
    const float* __restrict__ par, const float* __restrict__ pai)
{
    int bj = blockIdx.x;          // b*N + j
    int b  = bj >> 10;
    float sRj = g_sRj[bj], sIj = g_sIj[bj];
    float a_r = par[0], a_i = pai[0];
    const float* sRi = g_sRi + (b << 10);
    const float* sIi = g_sIi + (b << 10);
    float acc = 0.f;
#pragma unroll
    for (int t = 0; t < N_ / 128; t++) {
        int i = threadIdx.x + t * 128;
        float sr = sRi[i] + sRj;
        float si = sIi[i] + sIj;
        float pr = sr >= 0.f ? sr : a_r * sr;
        float pi = si >= 0.f ? si : a_i * si;
        float r2 = pr * pr + pi * pi;
        float inv = rsqrtf(fmaxf(r2, 1e-30f));
        float mag = r2 * inv;
        acc += __expf(mag);
    }
    __shared__ float sred[4];
#pragma unroll
    for (int off = 16; off; off >>= 1) acc += __shfl_xor_sync(0xffffffffu, acc, off);
    if ((threadIdx.x & 31) == 0) sred[threadIdx.x >> 5] = acc;
    __syncthreads();
    if (threadIdx.x == 0) {
        float t = sred[0] + sred[1] + sred[2] + sred[3];
        g_rsum[bj] = 1.f / t;
    }
}

// ============================================================
// Fused kernel: each block owns 16 rows i of batch b and produces
// out[b, i, :] completely.
//   Phase A: P[i][m][o] = sum_c X[b,i,c] * w[m,c,o]  (FMA-bound)
//            w staged per-m via 32KB smem buffer; P stashed to the
//            same buffer afterward (frees registers for Phase B).
//   Phase B: rowR/rowI[i][m] = sum_j L[b,m,i,j]*a(i,j) (DRAM-bound)
//            one warp per 4 rows; results to smem.
//   Combine: out = sum_m rowR*PR - rowI*PI (+imag twin).
// Odd blocks run B then A; even blocks A then B -> phases overlap
// chip-wide. Grid = 512 = one wave (~3.5 blocks/SM).
// ============================================================
#define FMA4(acc, s, v) \
    acc.x += (s) * (v).x; acc.y += (s) * (v).y; \
    acc.z += (s) * (v).z; acc.w += (s) * (v).w;

__global__ void __launch_bounds__(128, 4) k34_fused(
    const float* __restrict__ Xr, const float* __restrict__ Xi,
    const float* __restrict__ Lr, const float* __restrict__ Li,
    const float4* __restrict__ wr4, const float4* __restrict__ wi4,
    const float* __restrict__ par, const float* __restrict__ pai,
    float* __restrict__ out)
{
    __shared__ float4 wbuf[2048];        // wr[m] | wi[m]; later: P stash
    __shared__ float4 xbuf[2][256];      // 16 i x 16 f4 (r/i)
    __shared__ float rowR_s[16][4], rowI_s[16][4];

    const int tid   = threadIdx.x;
    const int bx    = blockIdx.x;
    const int b     = bx >> 6;
    const int ibase = (bx & 63) << 4;
    const int i_loc = tid >> 3;          // 0..15
    const int og    = tid & 7;           // o = og*8 .. og*8+7
    const int lane  = tid & 31;
    const int warp  = tid >> 5;          // 0..3

    // Phase A accumulators (live only during A, then stashed)
    float4 PRa[4], PRb[4], PIa[4], PIb[4];
#pragma unroll
    for (int m = 0; m < 4; m++) {
        PRa[m] = make_float4(0.f,0.f,0.f,0.f);
        PRb[m] = make_float4(0.f,0.f,0.f,0.f);
        PIa[m] = make_float4(0.f,0.f,0.f,0.f);
        PIb[m] = make_float4(0.f,0.f,0.f,0.f);
    }

    // X tile load (needed by Phase A only; cheap, done up front)
    {
        const float4* XrG = (const float4*)Xr + ((size_t)b * N_ + ibase) * (C_/4);
        const float4* XiG = (const float4*)Xi + ((size_t)b * N_ + ibase) * (C_/4);
#pragma unroll
        for (int r = 0; r < 2; r++) {
            int e = r * 128 + tid;
            xbuf[0][e] = XrG[e];
            xbuf[1][e] = XiG[e];
        }
    }

    const float a_r = par[0], a_i = pai[0];

#pragma unroll 1
    for (int ph = 0; ph < 2; ph++) {
        if (((bx ^ ph) & 1) == 0) {
            // ---------------- Phase A ----------------
#pragma unroll
            for (int m = 0; m < 4; m++) {
                __syncthreads();   // protect wbuf from previous use
#pragma unroll
                for (int r = 0; r < 8; r++) {
                    int e = r * 128 + tid;
                    wbuf[e]        = wr4[(m << 10) + e];
                    wbuf[1024 + e] = wi4[(m << 10) + e];
                }
                __syncthreads();
#pragma unroll 1
                for (int cq = 0; cq < 16; cq++) {
                    float4 xrv = xbuf[0][i_loc * 16 + cq];
                    float4 xiv = xbuf[1][i_loc * 16 + cq];
                    const float* fxr = (const float*)&xrv;
                    const float* fxi = (const float*)&xiv;
#pragma unroll
                    for (int ci = 0; ci < 4; ci++) {
                        int c = cq * 4 + ci;
                        float xr = fxr[ci], xi = fxi[ci];
                        float4 w0 = wbuf[c * 16 + og * 2];
                        float4 w1 = wbuf[c * 16 + og * 2 + 1];
                        float4 v0 = wbuf[1024 + c * 16 + og * 2];
                        float4 v1 = wbuf[1024 + c * 16 + og * 2 + 1];
                        FMA4(PRa[m], xr, w0);  FMA4(PRb[m], xr, w1);
                        FMA4(PIa[m], xi, v0);  FMA4(PIb[m], xi, v1);
                    }
                }
            }
            // stash P into wbuf (layout [q*128 + tid] -> conflict-free)
            __syncthreads();       // everyone done reading wbuf
#pragma unroll
            for (int m = 0; m < 4; m++) {
                wbuf[(m * 4 + 0) * 128 + tid] = PRa[m];
                wbuf[(m * 4 + 1) * 128 + tid] = PRb[m];
                wbuf[(m * 4 + 2) * 128 + tid] = PIa[m];
                wbuf[(m * 4 + 3) * 128 + tid] = PIb[m];
            }
        } else {
            // ---------------- Phase B ----------------
            // warp handles rows ig = ibase + warp*4 + it, it = 0..3
#pragma unroll 1
            for (int it = 0; it < 4; it++) {
                int ig = ibase + warp * 4 + it;
                float sRiv = g_sRi[(b << 10) + ig];
                float sIiv = g_sIi[(b << 10) + ig];
                float accR[4] = {0.f,0.f,0.f,0.f};
                float accI[4] = {0.f,0.f,0.f,0.f};
#pragma unroll 1
                for (int jq = 0; jq < 8; jq++) {
                    int j0  = jq * 128 + lane * 4;
                    int bj0 = (b << 10) + j0;
                    float4 sRj4 = *(const float4*)(g_sRj + bj0);
                    float4 sIj4 = *(const float4*)(g_sIj + bj0);
                    float4 rs4  = *(const float4*)(g_rsum + bj0);
                    const float* srj = (const float*)&sRj4;
                    const float* sij = (const float*)&sIj4;
                    const float* rsv = (const float*)&rs4;
                    float ar[4], ai[4];
#pragma unroll
                    for (int k = 0; k < 4; k++) {
                        float sr = sRiv + srj[k];
                        float si = sIiv + sij[k];
                        float pr = sr >= 0.f ? sr : a_r * sr;
                        float pi = si >= 0.f ? si : a_i * si;
                        float r2 = pr * pr + pi * pi;
                        float inv = rsqrtf(fmaxf(r2, 1e-30f));
                        float e = __expf(r2 * inv);
                        float sc = e * inv * rsv[k];
                        ar[k] = sc * pr;
                        ai[k] = sc * pi;
                    }
#pragma unroll
                    for (int m = 0; m < 4; m++) {
                        size_t base = (((size_t)((b << 2) + m) << 10) + ig) << 10;
                        float4 lr = *(const float4*)(Lr + base + j0);
                        float4 li = *(const float4*)(Li + base + j0);
                        accR[m] += lr.x * ar[0] - li.x * ai[0];
                        accR[m] += lr.y * ar[1] - li.y * ai[1];
                        accR[m] += lr.z * ar[2] - li.z * ai[2];
                        accR[m] += lr.w * ar[3] - li.w * ai[3];
                        accI[m] += lr.x * ai[0] + li.x * ar[0];
                        accI[m] += lr.y * ai[1] + li.y * ar[1];
                        accI[m] += lr.z * ai[2] + li.z * ar[2];
                        accI[m] += lr.w * ai[3] + li.w * ar[3];
                    }
                }
                // warp-reduce 8 values -> rowR_s / rowI_s
#pragma unroll
                for (int q = 0; q < 8; q++) {
                    float x = (q < 4) ? accR[q] : accI[q - 4];
#pragma unroll
                    for (int off = 16; off; off >>= 1)
                        x += __shfl_xor_sync(0xffffffffu, x, off);
                    if (lane == 0) {
                        if (q < 4) rowR_s[warp * 4 + it][q]     = x;
                        else       rowI_s[warp * 4 + it][q - 4] = x;
                    }
                }
            }
        }
    }

    __syncthreads();   // rowR_s/rowI_s + P stash all visible

    // ---------------- Combine + store ----------------
    float4 rea = make_float4(0.f,0.f,0.f,0.f);
    float4 reb = make_float4(0.f,0.f,0.f,0.f);
    float4 ima = make_float4(0.f,0.f,0.f,0.f);
    float4 imb = make_float4(0.f,0.f,0.f,0.f);
#pragma unroll
    for (int m = 0; m < 4; m++) {
        float a  = rowR_s[i_loc][m];
        float bi = rowI_s[i_loc][m];
        float4 pra = wbuf[(m * 4 + 0) * 128 + tid];
        float4 prb = wbuf[(m * 4 + 1) * 128 + tid];
        float4 pia = wbuf[(m * 4 + 2) * 128 + tid];
        float4 pib = wbuf[(m * 4 + 3) * 128 + tid];
        rea.x += a * pra.x - bi * pia.x;  rea.y += a * pra.y - bi * pia.y;
        rea.z += a * pra.z - bi * pia.z;  rea.w += a * pra.w - bi * pia.w;
        reb.x += a * prb.x - bi * pib.x;  reb.y += a * prb.y - bi * pib.y;
        reb.z += a * prb.z - bi * pib.z;  reb.w += a * prb.w - bi * pib.w;
        ima.x += bi * pra.x + a * pia.x;  ima.y += bi * pra.y + a * pia.y;
        ima.z += bi * pra.z + a * pia.z;  ima.w += bi * pra.w + a * pia.w;
        imb.x += bi * prb.x + a * pib.x;  imb.y += bi * prb.y + a * pib.y;
        imb.z += bi * prb.z + a * pib.z;  imb.w += bi * prb.w + a * pib.w;
    }
    size_t bn16 = ((size_t)b * N_ + ibase + i_loc) * 16;
    float4* o4 = (float4*)out;
    o4[bn16 + og * 2]     = rea;                  // real
    o4[bn16 + og * 2 + 1] = reb;
    o4[(size_t)BN * 16 + bn16 + og * 2]     = ima; // imag
    o4[(size_t)BN * 16 + bn16 + og * 2 + 1] = imb;
}

// ============================================================
extern "C" void kernel_launch(void* const* d_in, const int* in_sizes, int n_in,
                              void* d_out, int out_size)
{
    const float* Xr  = (const float*)d_in[0];
    const float* Xi  = (const float*)d_in[1];
    const float* Lr  = (const float*)d_in[2];
    const float* Li  = (const float*)d_in[3];
    const float* wr  = (const float*)d_in[4];
    const float* wi  = (const float*)d_in[5];
    const float* awr = (const float*)d_in[6];
    const float* awi = (const float*)d_in[7];
    const float* abr = (const float*)d_in[8];
    const float* abi = (const float*)d_in[9];
    const float* par = (const float*)d_in[10];
    const float* pai = (const float*)d_in[11];
    float* out = (float*)d_out;

    k1_proj  <<<BN / 8, 256>>>(Xr, Xi, awr, awi, abr, abi);
    k2_sumexp<<<BN,     128>>>(par, pai);
    k34_fused<<<512,    128>>>(Xr, Xi, Lr, Li,
                               (const float4*)wr, (const float4*)wi,
                               par, pai, out);
}

// round 8
// speedup vs baseline: 1.5936x; 1.5936x over previous
#include <cuda_runtime.h>

// Problem constants
#define B_  8
#define N_  1024
#define C_  64
#define O_  64
#define KM  4          // K+1
#define BN  (B_*N_)    // 8192

// -------- device scratch --------
__device__ float g_sRi[BN], g_sIi[BN], g_sRj[BN], g_sIj[BN];
__device__ float g_rsum[BN];                   // 1 / sum_i exp(mag) per (b,j)
__device__ float g_rowR[KM*BN], g_rowI[KM*BN]; // (b*4+m)*N + i
__device__ float g_PR[BN*KM*O_], g_PI[BN*KM*O_]; // [bn][m][o]

// ============================================================
// Kernel 1: per-(b,n) attention projections. One warp per (b,n).
// ============================================================
__global__ void __launch_bounds__(256) k1_proj(
    const float* __restrict__ Xr, const float* __restrict__ Xi,
    const float* __restrict__ awr, const float* __restrict__ awi,
    const float* __restrict__ abr, const float* __restrict__ abi)
{
    int warp = (blockIdx.x * blockDim.x + threadIdx.x) >> 5;
    int lane = threadIdx.x & 31;
    if (warp >= BN) return;
    const float* xr = Xr + warp * C_;
    const float* xi = Xi + warp * C_;
    float sRi = 0.f, sIi = 0.f, sRj = 0.f, sIj = 0.f;
#pragma unroll
    for (int t = 0; t < 2; t++) {
        int c = lane + t * 32;
        float a = xr[c], b = xi[c];
        float wri = awr[c],      wii = awi[c];
        float wrj = awr[C_ + c], wij = awi[C_ + c];
        sRi += a * wri - b * wii;
        sIi += a * wii + b * wri;
        sRj += a * wrj - b * wij;
        sIj += a * wij + b * wrj;
    }
#pragma unroll
    for (int off = 16; off; off >>= 1) {
        sRi += __shfl_xor_sync(0xffffffffu, sRi, off);
        sIi += __shfl_xor_sync(0xffffffffu, sIi, off);
        sRj += __shfl_xor_sync(0xffffffffu, sRj, off);
        sIj += __shfl_xor_sync(0xffffffffu, sIj, off);
    }
    if (lane == 0) {
        g_sRi[warp] = sRi + abr[0];
        g_sIi[warp] = sIi + abi[0];
        g_sRj[warp] = sRj;
        g_sIj[warp] = sIj;
    }
}

// ============================================================
// Kernel 2: softmax denominator per (b,j): sum over i of exp(mag).
// ============================================================
__global__ void __launch_bounds__(128) k2_sumexp(
    const float* __restrict__ par, const float* __restrict__ pai)
{
    int bj = blockIdx.x;          // b*N + j
    int b  = bj >> 10;
    float sRj = g_sRj[bj], sIj = g_sIj[bj];
    float a_r = par[0], a_i = pai[0];
    const float* sRi = g_sRi + (b << 10);
    const float* sIi = g_sIi + (b << 10);
    float acc = 0.f;
#pragma unroll
    for (int t = 0; t < N_ / 128; t++) {
        int i = threadIdx.x + t * 128;
        float sr = sRi[i] + sRj;
        float si = sIi[i] + sIj;
        float pr = sr >= 0.f ? sr : a_r * sr;
        float pi = si >= 0.f ? si : a_i * si;
        float r2 = pr * pr + pi * pi;
        float inv = rsqrtf(fmaxf(r2, 1e-30f));
        float mag = r2 * inv;
        acc += __expf(mag);
    }
    __shared__ float sred[4];
#pragma unroll
    for (int off = 16; off; off >>= 1) acc += __shfl_xor_sync(0xffffffffu, acc, off);
    if ((threadIdx.x & 31) == 0) sred[threadIdx.x >> 5] = acc;
    __syncthreads();
    if (threadIdx.x == 0) {
        float t = sred[0] + sred[1] + sred[2] + sred[3];
        g_rsum[bj] = 1.f / t;
    }
}

// ============================================================
// Fused k34: role-specialized blocks, NO inter-role dependency.
//   blocks 0..255   : k3-role — stream L (DRAM-bound), warp-per-row,
//                     32 rows per block -> g_rowR/g_rowI.
//   blocks 256..767 : k4a-role — R6's k4 compute (FMA-bound),
//                     writes PR/PI to global scratch (no combine).
// Both roles co-resident -> DRAM and FMA pipes overlap chip-wide.
// ============================================================
#define FMA4(acc, s, v) \
    acc.x += (s) * (v).x; acc.y += (s) * (v).y; \
    acc.z += (s) * (v).z; acc.w += (s) * (v).w;

// swizzled index within an 8KB phase buffer: j in [0,64), q in [0,4)
#define XSW(j, q) (((j) << 2) | ((q) ^ ((j) & 3) ^ (((j) >> 2) & 3)))

__global__ void __launch_bounds__(128, 4) k34(
    const float* __restrict__ Xr, const float* __restrict__ Xi,
    const float* __restrict__ Lr, const float* __restrict__ Li,
    const float4* __restrict__ wr4, const float4* __restrict__ wi4,
    const float* __restrict__ par, const float* __restrict__ pai)
{
    __shared__ float4 wr_s[KM * C_ * 4];     // 16 KB (k4a role)
    __shared__ float4 wi_s[KM * C_ * 4];     // 16 KB
    __shared__ float4 x_s[2][2][256];        // 16 KB

    const int bx  = blockIdx.x;
    const int tid = threadIdx.x;

    if (bx < 256) {
        // ================= k3-role =================
        const int b     = bx >> 5;           // 32 blocks per batch
        const int ibase = (bx & 31) << 5;    // 32 rows
        const int warp  = tid >> 5;
        const int lane  = tid & 31;
        const float a_r = par[0], a_i = pai[0];

#pragma unroll 1
        for (int rr = 0; rr < 8; rr++) {
            int ig = ibase + warp * 8 + rr;
            float sRiv = g_sRi[(b << 10) + ig];
            float sIiv = g_sIi[(b << 10) + ig];
            float accR[4] = {0.f,0.f,0.f,0.f};
            float accI[4] = {0.f,0.f,0.f,0.f};
#pragma unroll 1
            for (int ch = 0; ch < 8; ch++) {
                int j0  = ch * 128 + lane * 4;
                int bj0 = (b << 10) + j0;
                float4 sRj4 = *(const float4*)(g_sRj + bj0);
                float4 sIj4 = *(const float4*)(g_sIj + bj0);
                float4 rs4  = *(const float4*)(g_rsum + bj0);
                const float* srj = (const float*)&sRj4;
                const float* sij = (const float*)&sIj4;
                const float* rsv = (const float*)&rs4;
                float ar[4], ai[4];
#pragma unroll
                for (int k = 0; k < 4; k++) {
                    float sr = sRiv + srj[k];
                    float si = sIiv + sij[k];
                    float pr = sr >= 0.f ? sr : a_r * sr;
                    float pi = si >= 0.f ? si : a_i * si;
                    float r2 = pr * pr + pi * pi;
                    float inv = rsqrtf(fmaxf(r2, 1e-30f));
                    float e = __expf(r2 * inv);
                    float sc = e * inv * rsv[k];
                    ar[k] = sc * pr;
                    ai[k] = sc * pi;
                }
#pragma unroll
                for (int m = 0; m < 4; m++) {
                    size_t base = (((size_t)((b << 2) + m) << 10) + ig) << 10;
                    float4 lr = *(const float4*)(Lr + base + j0);
                    float4 li = *(const float4*)(Li + base + j0);
                    accR[m] += lr.x * ar[0] - li.x * ai[0];
                    accR[m] += lr.y * ar[1] - li.y * ai[1];
                    accR[m] += lr.z * ar[2] - li.z * ai[2];
                    accR[m] += lr.w * ar[3] - li.w * ai[3];
                    accI[m] += lr.x * ai[0] + li.x * ar[0];
                    accI[m] += lr.y * ai[1] + li.y * ar[1];
                    accI[m] += lr.z * ai[2] + li.z * ar[2];
                    accI[m] += lr.w * ai[3] + li.w * ar[3];
                }
            }
            // warp-reduce 8 values, lane0 writes
#pragma unroll
            for (int q = 0; q < 8; q++) {
                float x = (q < 4) ? accR[q] : accI[q - 4];
#pragma unroll
                for (int off = 16; off; off >>= 1)
                    x += __shfl_xor_sync(0xffffffffu, x, off);
                if (lane == 0) {
                    int m = q & 3;
                    if (q < 4) g_rowR[((b << 2) + m) * N_ + ig] = x;
                    else       g_rowI[((b << 2) + m) * N_ + ig] = x;
                }
            }
        }
        return;
    }

    // ================= k4a-role (R6 k4, P to global) =================
    const int t4  = bx - 256;                // 0..511
    const int og  = tid & 3;
    const int jl  = tid >> 2;                // 0..31
    const int jg  = t4 & 127;
    const int oq  = t4 >> 7;                 // 0..3
    const int jbase = jg * 64;

    const float4* XrG = (const float4*)Xr + (size_t)jbase * 16;
    const float4* XiG = (const float4*)Xi + (size_t)jbase * 16;

    // ---- w slice load (resident) ----
#pragma unroll
    for (int r = 0; r < 8; r++) {
        int e  = r * 128 + tid;              // 0..1023
        int mc = e >> 2, o2 = e & 3;
        wr_s[e] = wr4[mc * 16 + oq * 4 + o2];
        wi_s[e] = wi4[mc * 16 + oq * 4 + o2];
    }

    // ---- X phase 0 load ----
#pragma unroll
    for (int r = 0; r < 2; r++) {
        int e = r * 128 + tid;               // 0..255
        int j = e >> 2, q = e & 3;
        int si = XSW(j, q);
        x_s[0][0][si] = XrG[j * 16 + q];
        x_s[0][1][si] = XiG[j * 16 + q];
    }
    __syncthreads();

    float4 PR0[4], PI0[4], PR1[4], PI1[4];
#pragma unroll
    for (int m = 0; m < 4; m++) {
        PR0[m] = make_float4(0.f,0.f,0.f,0.f); PI0[m] = make_float4(0.f,0.f,0.f,0.f);
        PR1[m] = make_float4(0.f,0.f,0.f,0.f); PI1[m] = make_float4(0.f,0.f,0.f,0.f);
    }

    const int j0 = jl, j1 = jl + 32;

#pragma unroll
    for (int p = 0; p < 4; p++) {
        int buf = p & 1;
        if (p < 3) {
            int nb = buf ^ 1;
#pragma unroll
            for (int r = 0; r < 2; r++) {
                int e = r * 128 + tid;
                int j = e >> 2, q = e & 3;
                int si = XSW(j, q);
                x_s[nb][0][si] = XrG[j * 16 + (p + 1) * 4 + q];
                x_s[nb][1][si] = XiG[j * 16 + (p + 1) * 4 + q];
            }
        }
#pragma unroll
        for (int q = 0; q < 4; q++) {
            float4 xr0 = x_s[buf][0][XSW(j0, q)];
            float4 xi0 = x_s[buf][1][XSW(j0, q)];
            float4 xr1 = x_s[buf][0][XSW(j1, q)];
            float4 xi1 = x_s[buf][1][XSW(j1, q)];
            const float* fxr0 = (const float*)&xr0;
            const float* fxi0 = (const float*)&xi0;
            const float* fxr1 = (const float*)&xr1;
            const float* fxi1 = (const float*)&xi1;
#pragma unroll
            for (int ci = 0; ci < 4; ci++) {
                int c = p * 16 + q * 4 + ci;
                float a0 = fxr0[ci], b0 = fxi0[ci];
                float a1 = fxr1[ci], b1 = fxi1[ci];
#pragma unroll
                for (int m = 0; m < 4; m++) {
                    float4 wr = wr_s[((m << 6) + c) * 4 + og];
                    float4 wi = wi_s[((m << 6) + c) * 4 + og];
                    FMA4(PR0[m], a0, wr);
                    FMA4(PI0[m], b0, wi);
                    FMA4(PR1[m], a1, wr);
                    FMA4(PI1[m], b1, wi);
                }
            }
        }
        __syncthreads();
    }

    // ---- store P to global scratch: g_P[bn*256 + m*64 + o] ----
    float4* PR4 = (float4*)g_PR;
    float4* PI4 = (float4*)g_PI;
#pragma unroll
    for (int jt = 0; jt < 2; jt++) {
        int jj = jbase + jl + jt * 32;
        size_t base = (size_t)jj * 64 + oq * 4 + og;   // float4 units
#pragma unroll
        for (int m = 0; m < 4; m++) {
            PR4[base + m * 16] = jt ? PR1[m] : PR0[m];
            PI4[base + m * 16] = jt ? PI1[m] : PI0[m];
        }
    }
}

// ============================================================
// k4b: combine. out = rowR*PR - rowI*PI ; imag = rowI*PR + rowR*PI
// Thread = (bn, og). Streams P (16.8MB) + writes out (4MB).
// ============================================================
__global__ void __launch_bounds__(256) k4b_combine(float* __restrict__ out)
{
    int gid = blockIdx.x * 256 + threadIdx.x;    // bn*16 + og
    int bn  = gid >> 4;
    int og  = gid & 15;
    int b   = bn >> 10, j = bn & 1023;

    const float4* PR4 = (const float4*)g_PR;
    const float4* PI4 = (const float4*)g_PI;
    size_t base = (size_t)bn * 64 + og;

    float4 re = make_float4(0.f,0.f,0.f,0.f);
    float4 im = make_float4(0.f,0.f,0.f,0.f);
#pragma unroll
    for (int m = 0; m < 4; m++) {
        float a  = g_rowR[((b << 2) + m) * N_ + j];
        float bi = g_rowI[((b << 2) + m) * N_ + j];
        float4 pr = PR4[base + m * 16];
        float4 pi = PI4[base + m * 16];
        re.x += a * pr.x - bi * pi.x;  re.y += a * pr.y - bi * pi.y;
        re.z += a * pr.z - bi * pi.z;  re.w += a * pr.w - bi * pi.w;
        im.x += bi * pr.x + a * pi.x;  im.y += bi * pr.y + a * pi.y;
        im.z += bi * pr.z + a * pi.z;  im.w += bi * pr.w + a * pi.w;
    }
    float4* o4 = (float4*)out;
    o4[(size_t)bn * 16 + og] = re;
    o4[(size_t)BN * 16 + (size_t)bn * 16 + og] = im;
}

// ============================================================
extern "C" void kernel_launch(void* const* d_in, const int* in_sizes, int n_in,
                              void* d_out, int out_size)
{
    const float* Xr  = (const float*)d_in[0];
    const float* Xi  = (const float*)d_in[1];
    const float* Lr  = (const float*)d_in[2];
    const float* Li  = (const float*)d_in[3];
    const float* wr  = (const float*)d_in[4];
    const float* wi  = (const float*)d_in[5];
    const float* awr = (const float*)d_in[6];
    const float* awi = (const float*)d_in[7];
    const float* abr = (const float*)d_in[8];
    const float* abi = (const float*)d_in[9];
    const float* par = (const float*)d_in[10];
    const float* pai = (const float*)d_in[11];
    float* out = (float*)d_out;

    k1_proj    <<<BN / 8, 256>>>(Xr, Xi, awr, awi, abr, abi);
    k2_sumexp  <<<BN,     128>>>(par, pai);
    k34        <<<768,    128>>>(Xr, Xi, Lr, Li,
                                 (const float4*)wr, (const float4*)wi,
                                 par, pai);
    k4b_combine<<<BN * 16 / 256, 256>>>(out);
}